// round 2
// baseline (speedup 1.0000x reference)
#include <cuda_runtime.h>
#include <cstdint>

// Problem constants
#define Bz 8
#define Tz 1024
#define Dz 1024
#define Qz 8
#define Kz 4096
#define dz 128
#define Mz (Bz*Tz)               // 8192 rows
#define OUT_ELEMS (Mz*Dz)        // 8388608
#define IDX_ELEMS (Mz*Qz)        // 65536

// Scratch (device globals: allocation-free rule)
__device__ float g_xn[(size_t)Mz*Dz];   // rmsnorm'd input, 32MB
__device__ float g_hc2[Qz*Kz];          // 0.5 * ||code||^2
__device__ int   g_idx[Mz*Qz];          // argmin indices

// ---- f32x2 packed-FMA helpers (sm_103a FFMA2) ----
static __device__ __forceinline__ unsigned long long pack2(float v){
    unsigned long long r; unsigned u = __float_as_uint(v);
    asm("mov.b64 %0, {%1, %1};" : "=l"(r) : "r"(u));
    return r;
}
static __device__ __forceinline__ void ffma2(unsigned long long& d,
                                             unsigned long long a,
                                             unsigned long long b){
    asm("fma.rn.f32x2 %0, %1, %2, %3;" : "=l"(d) : "l"(a), "l"(b), "l"(d));
}
static __device__ __forceinline__ float2 unpack2(unsigned long long v){
    unsigned lo, hi;
    asm("mov.b64 {%0, %1}, %2;" : "=r"(lo), "=r"(hi) : "l"(v));
    return make_float2(__uint_as_float(lo), __uint_as_float(hi));
}

// ---------------- Kernel 1: input rmsnorm ----------------
__global__ void rmsnorm_in_kernel(const float* __restrict__ x,
                                  const float* __restrict__ w){
    int m = blockIdx.x, t = threadIdx.x;
    float4 v = reinterpret_cast<const float4*>(x)[(size_t)m*256 + t];
    float ss = v.x*v.x + v.y*v.y + v.z*v.z + v.w*v.w;
    __shared__ float sred[8];
    __shared__ float s_scale;
    #pragma unroll
    for (int o = 16; o > 0; o >>= 1) ss += __shfl_xor_sync(0xffffffffu, ss, o);
    if ((t & 31) == 0) sred[t >> 5] = ss;
    __syncthreads();
    if (t < 8){
        float s2 = sred[t];
        #pragma unroll
        for (int o = 4; o > 0; o >>= 1) s2 += __shfl_xor_sync(0xffu, s2, o);
        if (t == 0){
            float mean = s2 * (1.0f/1024.0f) + 1e-5f;
            float r = rsqrtf(mean);
            r = r * (1.5f - 0.5f*mean*r*r);   // one Newton step
            s_scale = r;
        }
    }
    __syncthreads();
    float sc = s_scale;
    float4 wv = reinterpret_cast<const float4*>(w)[t];
    float4 o4 = make_float4(v.x*sc*wv.x, v.y*sc*wv.y, v.z*sc*wv.z, v.w*sc*wv.w);
    reinterpret_cast<float4*>(g_xn)[(size_t)m*256 + t] = o4;
}

// ---------------- Kernel 2: 0.5 * ||code||^2 ----------------
__global__ void hc2_kernel(const float* __restrict__ cb){
    int code = blockIdx.x*8 + (threadIdx.x >> 5);
    int lane = threadIdx.x & 31;
    float4 c = reinterpret_cast<const float4*>(cb)[(size_t)code*32 + lane];
    float s = c.x*c.x + c.y*c.y + c.z*c.z + c.w*c.w;
    #pragma unroll
    for (int o = 16; o > 0; o >>= 1) s += __shfl_xor_sync(0xffffffffu, s, o);
    if (lane == 0) g_hc2[code] = 0.5f*s;
}

// ---------------- Kernel 3: fused GEMM + argmin ----------------
// Block: 64 rows x (all K in 64-col chunks), one q per blockIdx.y.
// score = 0.5*c2 - x.c   (same argmin as full d2)
#define PAD 68
#define SMEM_ARGMIN (2*128*PAD*4)   // 69632 bytes

__global__ void __launch_bounds__(256)
argmin_kernel(const float* __restrict__ cb, float* __restrict__ tail){
    extern __shared__ float sm[];
    float* As = sm;                 // [k][row] 128 x 68 (64 rows used)
    float* Bs = sm + 128*PAD;       // [k][col] 128 x 68 (64 cols used)

    int tid = threadIdx.x;
    int tx = tid & 15, ty = tid >> 4;
    int q  = blockIdx.y;
    int m0 = blockIdx.x * 64;

    const float* xq  = g_xn + (size_t)m0*Dz + q*dz;     // row stride Dz
    const float* cbq = cb + (size_t)q*Kz*dz;

    // Load A tile (64 rows x 128 k), transposed into As[k][row].
    // Warp lanes run along k -> coalesced gmem reads; STS.128 per (k,rowquad).
    #pragma unroll
    for (int it = 0; it < 8; ++it){
        int u  = it*256 + tid;
        int k  = (u & 31) + ((u >> 9) << 5);
        int rg = (u >> 5) & 15;
        const float* p = xq + (size_t)(4*rg)*Dz + k;
        float a0 = p[0*Dz], a1 = p[1*Dz], a2 = p[2*Dz], a3 = p[3*Dz];
        *reinterpret_cast<float4*>(&As[k*PAD + 4*rg]) = make_float4(a0,a1,a2,a3);
    }

    float bestv[4] = {3.4e38f, 3.4e38f, 3.4e38f, 3.4e38f};
    int   besti[4] = {0,0,0,0};

    for (int chunk = 0; chunk < 64; ++chunk){
        int n0 = chunk*64;
        // Load B tile (64 cols x 128 k) transposed into Bs[k][col]
        #pragma unroll
        for (int it = 0; it < 8; ++it){
            int u  = it*256 + tid;
            int k  = (u & 31) + ((u >> 9) << 5);
            int cg = (u >> 5) & 15;
            const float* p = cbq + (size_t)(n0 + 4*cg)*dz + k;
            float b0 = p[0], b1 = p[dz], b2 = p[2*dz], b3 = p[3*dz];
            *reinterpret_cast<float4*>(&Bs[k*PAD + 4*cg]) = make_float4(b0,b1,b2,b3);
        }
        __syncthreads();

        // 4 rows x 4 cols microtile; rows packed in f32x2 pairs.
        unsigned long long a01acc[4] = {0ull,0ull,0ull,0ull};
        unsigned long long a23acc[4] = {0ull,0ull,0ull,0ull};
        const float* Ap = &As[4*ty];
        const float* Bp = &Bs[4*tx];
        #pragma unroll 8
        for (int k = 0; k < 128; ++k){
            ulonglong2 av = *reinterpret_cast<const ulonglong2*>(Ap + k*PAD);
            float4     bv = *reinterpret_cast<const float4*>(Bp + k*PAD);
            unsigned long long bb0 = pack2(bv.x);
            unsigned long long bb1 = pack2(bv.y);
            unsigned long long bb2 = pack2(bv.z);
            unsigned long long bb3 = pack2(bv.w);
            ffma2(a01acc[0], av.x, bb0); ffma2(a23acc[0], av.y, bb0);
            ffma2(a01acc[1], av.x, bb1); ffma2(a23acc[1], av.y, bb1);
            ffma2(a01acc[2], av.x, bb2); ffma2(a23acc[2], av.y, bb2);
            ffma2(a01acc[3], av.x, bb3); ffma2(a23acc[3], av.y, bb3);
        }
        __syncthreads();   // Bs consumed; safe to overwrite next chunk

        // Fused epilogue: running min of (0.5*c2 - xc)
        #pragma unroll
        for (int j = 0; j < 4; ++j){
            int n = n0 + 4*tx + j;
            float hc = __ldg(&g_hc2[q*Kz + n]);
            float2 s01 = unpack2(a01acc[j]);
            float2 s23 = unpack2(a23acc[j]);
            float s0 = hc - s01.x, s1 = hc - s01.y;
            float s2 = hc - s23.x, s3 = hc - s23.y;
            if (s0 < bestv[0]) { bestv[0] = s0; besti[0] = n; }
            if (s1 < bestv[1]) { bestv[1] = s1; besti[1] = n; }
            if (s2 < bestv[2]) { bestv[2] = s2; besti[2] = n; }
            if (s3 < bestv[3]) { bestv[3] = s3; besti[3] = n; }
        }
    }

    // Cross-thread reduction per row (16 tx lanes per row), tie -> lower idx
    __syncthreads();
    float* rv = sm;                                   // reuse smem: 64*16 floats
    int*   ri = reinterpret_cast<int*>(sm + 64*16);   // 64*16 ints
    #pragma unroll
    for (int i = 0; i < 4; ++i){
        rv[(4*ty+i)*16 + tx] = bestv[i];
        ri[(4*ty+i)*16 + tx] = besti[i];
    }
    __syncthreads();
    if (tid < 64){
        float bv = rv[tid*16]; int bi = ri[tid*16];
        #pragma unroll
        for (int t2 = 1; t2 < 16; ++t2){
            float v = rv[tid*16 + t2]; int id = ri[tid*16 + t2];
            if (v < bv || (v == bv && id < bi)) { bv = v; bi = id; }
        }
        int m = m0 + tid;
        g_idx[m*Qz + q] = bi;
        if (tail) tail[m*Qz + q] = (float)bi;
    }
}

// ---------------- Kernel 4: gather codes + output rmsnorm ----------------
__global__ void out_kernel(const float* __restrict__ cb,
                           const float* __restrict__ w,
                           float* __restrict__ out){
    int m = blockIdx.x, t = threadIdx.x;
    __shared__ int   sidx[8];
    __shared__ float s_scale;
    if (t < 8) sidx[t] = g_idx[m*Qz + t];
    __syncthreads();
    if (t < 8){
        // sum of quant^2 over the row = sum_q 2*hc2[q][idx_q]
        float p = g_hc2[t*Kz + sidx[t]];
        #pragma unroll
        for (int o = 4; o > 0; o >>= 1) p += __shfl_xor_sync(0xffu, p, o);
        if (t == 0){
            float mean = (2.0f*p) * (1.0f/1024.0f) + 1e-5f;
            float r = rsqrtf(mean);
            r = r * (1.5f - 0.5f*mean*r*r);
            s_scale = r;
        }
    }
    __syncthreads();
    int q = t >> 5, lane = t & 31;
    float4 c = reinterpret_cast<const float4*>(cb)[((size_t)q*Kz + sidx[q])*32 + lane];
    float sc = s_scale;
    float4 wv = reinterpret_cast<const float4*>(w)[t];
    reinterpret_cast<float4*>(out)[(size_t)m*256 + t] =
        make_float4(c.x*sc*wv.x, c.y*sc*wv.y, c.z*sc*wv.z, c.w*sc*wv.w);
}

// ---------------- Launch ----------------
extern "C" void kernel_launch(void* const* d_in, const int* in_sizes, int n_in,
                              void* d_out, int out_size){
    const float* x     = (const float*)d_in[0];
    const float* cb    = (const float*)d_in[1];
    const float* w_in  = (const float*)d_in[2];
    const float* w_out = (const float*)d_in[3];
    float* out = (float*)d_out;
    float* tail = (out_size >= OUT_ELEMS + IDX_ELEMS) ? (out + OUT_ELEMS) : nullptr;

    cudaFuncSetAttribute((const void*)argmin_kernel,
                         cudaFuncAttributeMaxDynamicSharedMemorySize, SMEM_ARGMIN);

    rmsnorm_in_kernel<<<Mz, 256>>>(x, w_in);
    hc2_kernel<<<(Qz*Kz)/8, 256>>>(cb);
    argmin_kernel<<<dim3(Mz/64, Qz), 256, SMEM_ARGMIN>>>(cb, tail);
    out_kernel<<<Mz, 256>>>(cb, w_out, out);
}